// round 9
// baseline (speedup 1.0000x reference)
#include <cuda_runtime.h>

// LieTransport, two-phase with PDL overlap:
//  1) precompute per-(b,y,x) bilinear record packed in ONE float4:
//       .x = base corner float4-offset (bitcast int)
//       .y = packed {dx (lo16), dy (hi16)} corner steps (bitcast int)
//       .z = wx, .w = wy
//  2) main gather kernel: 1 float4/thread, 16 lanes/pixel, 2D grid
//     (x = pixel-block, y = b*C + c) for minimal index decode.
// Corner addresses: base, base+dx, base+dy, base+dx+dy.

#define B 4
#define C 16
#define H 128
#define W 128
#define R 64
#define R4 (R / 4)            // 16 float4 per pixel
#define HW (H * W)
#define NPIX (B * HW)         // 65536 records

__device__ float4 g_rec[NPIX];

__global__ void __launch_bounds__(256)
precompute_kernel(const float* __restrict__ flow,
                  const float* __restrict__ dt)
{
    int t = blockIdx.x * blockDim.x + threadIdx.x;   // 0 .. NPIX-1
    int x = t & (W - 1);
    int y = (t >> 7) & (H - 1);
    int b = t >> 14;

    float d   = __ldg(&dt[b]);
    float fdx = __ldg(&flow[((b * 2 + 0) * H + y) * W + x]);
    float fdy = __ldg(&flow[((b * 2 + 1) * H + y) * W + x]);

    float gx = fmaf((float)x, 2.0f / (W - 1), -1.0f) - fdx * d;
    float gy = fmaf((float)y, 2.0f / (H - 1), -1.0f) - fdy * d;

    float xs = fminf(fmaxf(((gx + 1.0f) * (float)W - 1.0f) * 0.5f, 0.0f), (float)(W - 1));
    float ys = fminf(fmaxf(((gy + 1.0f) * (float)H - 1.0f) * 0.5f, 0.0f), (float)(H - 1));

    float x0f = floorf(xs);
    float y0f = floorf(ys);

    int x0 = (int)x0f;
    int y0 = (int)y0f;
    int dx = (x0 < W - 1) ? R4 : 0;            // step to x1 (float4 units)
    int dy = (y0 < H - 1) ? (W * R4) : 0;      // step to y1 (float4 units)

    float4 rec;
    rec.x = __int_as_float((y0 * W + x0) * R4);
    rec.y = __int_as_float(dx | (dy << 16));
    rec.z = xs - x0f;
    rec.w = ys - y0f;
    g_rec[t] = rec;

#if __CUDA_ARCH__ >= 900
    cudaTriggerProgrammaticLaunchCompletion();
#endif
}

__device__ __forceinline__ float4 f4_lerp(float4 a, float4 b, float t) {
    float4 r;
    r.x = fmaf(t, b.x - a.x, a.x);
    r.y = fmaf(t, b.y - a.y, a.y);
    r.z = fmaf(t, b.z - a.z, a.z);
    r.w = fmaf(t, b.w - a.w, a.w);
    return r;
}

__global__ void __launch_bounds__(256)
lie_transport_kernel(const float4* __restrict__ h4,
                     float4* __restrict__ out4)
{
    // grid: x = pixel-block (16 pixels), y = b*C + c
    int tid = threadIdx.x;

    // record index: (b)*HW + pixel
    int p = (blockIdx.y >> 4) * HW + (blockIdx.x << 4) + (tid >> 4);

    // image base for this (b,c) in float4 units, plus r4 lane
    int base = blockIdx.y * (HW * R4) + (tid & (R4 - 1));

#if __CUDA_ARCH__ >= 900
    cudaGridDependencySynchronize();
#endif

    float4 rec = __ldg(&g_rec[p]);
    int pk  = __float_as_int(rec.y);
    int dx  = pk & 0xFFFF;
    int dy  = pk >> 16;

    const float4* h00 = h4 + base + __float_as_int(rec.x);

    float4 v00 = __ldg(h00);
    float4 v01 = __ldg(h00 + dx);
    float4 v10 = __ldg(h00 + dy);
    float4 v11 = __ldg(h00 + dy + dx);

    float4 top = f4_lerp(v00, v01, rec.z);
    float4 bot = f4_lerp(v10, v11, rec.z);
    out4[blockIdx.y * (HW * R4) + (blockIdx.x << 8) + tid] = f4_lerp(top, bot, rec.w);
}

extern "C" void kernel_launch(void* const* d_in, const int* in_sizes, int n_in,
                              void* d_out, int out_size)
{
    const float* h_prev = nullptr;
    const float* flow   = nullptr;
    const float* dt     = nullptr;
    for (int i = 0; i < n_in; ++i) {
        if (in_sizes[i] == B * C * H * W * R)      h_prev = (const float*)d_in[i];
        else if (in_sizes[i] == B * 2 * H * W)     flow   = (const float*)d_in[i];
        else if (in_sizes[i] == B)                 dt     = (const float*)d_in[i];
    }

    // Primary: compute records
    precompute_kernel<<<NPIX / 256, 256>>>(flow, dt);

    // Secondary: PDL launch overlapping the primary's tail
    cudaLaunchConfig_t cfg = {};
    cfg.gridDim  = dim3(HW / 16, B * C);       // 1024 x 64 blocks
    cfg.blockDim = dim3(256);
    cfg.dynamicSmemBytes = 0;
    cfg.stream = 0;
    cudaLaunchAttribute attrs[1];
    attrs[0].id = cudaLaunchAttributeProgrammaticStreamSerialization;
    attrs[0].val.programmaticStreamSerializationAllowed = 1;
    cfg.attrs = attrs;
    cfg.numAttrs = 1;
    cudaLaunchKernelEx(&cfg, lie_transport_kernel,
                       (const float4*)h_prev, (float4*)d_out);
}